// round 6
// baseline (speedup 1.0000x reference)
#include <cuda_runtime.h>
#include <cuda_fp16.h>
#include <math.h>
#include <stdint.h>

#define BATCH 2
#define CH    512
#define CQ    64
#define NPIX  4096

typedef __half fp16;

// ---------------- static scratch ----------------
__device__ __align__(128) fp16  g_xTh[4L * NPIX * CH];   // [which*2+b][n][c] hi
__device__ __align__(128) fp16  g_xTl[4L * NPIX * CH];
__device__ __align__(128) fp16  g_xcTh[2L * NPIX * CH];  // [b][n][c]
__device__ __align__(128) fp16  g_xcTl[2L * NPIX * CH];
__device__ __align__(128) fp16  g_Wbch[128 * CH];        // [o(128)][c] (Wb;Wc)
__device__ __align__(128) fp16  g_Wbcl[128 * CH];
__device__ __align__(128) fp16  g_Wdh[CH * CH];
__device__ __align__(128) fp16  g_Wdl[CH * CH];
__device__ __align__(128) fp16  g_Ph[4L * NPIX * 128];   // [which*2+b][n][o]
__device__ __align__(128) fp16  g_Pl[4L * NPIX * 128];
__device__ __align__(128) fp16  g_Fh[(long)BATCH * CH * NPIX];  // [b][c][n]
__device__ __align__(128) fp16  g_Fl[(long)BATCH * CH * NPIX];
__device__ __align__(128) float g_S12[(size_t)BATCH * NPIX * NPIX];
__device__ __align__(128) float g_S21[(size_t)BATCH * NPIX * NPIX];
__device__ __align__(128) fp16  g_Ah[(size_t)BATCH * NPIX * NPIX];
__device__ __align__(128) fp16  g_Al[(size_t)BATCH * NPIX * NPIX];
__device__ float g_scal[4];
__device__ float g_bias2[128];

__device__ __forceinline__ void split2(float v, fp16& h, fp16& l) {
    h = __float2half_rn(v);
    l = __float2half_rn(v - __half2float(h));
}

// ---------------- prep ----------------
__global__ void prep_kernel(const float* bb, const float* bc,
                            const float* a, const float* b) {
    int t = threadIdx.x;
    if (t < 64)       g_bias2[t] = bb[t];
    else if (t < 128) g_bias2[t] = bc[t - 64];
    if (t == 0) { g_scal[0] = a[0]; g_scal[1] = b[0]; g_scal[2] = a[0] + b[0]; }
}

__global__ void split_kernel(const float* __restrict__ src,
                             fp16* __restrict__ hi, fp16* __restrict__ lo, int n) {
    int i = blockIdx.x * blockDim.x + threadIdx.x;
    if (i < n) { fp16 h, l; split2(src[i], h, l); hi[i] = h; lo[i] = l; }
}

__global__ void wbc_split_kernel(const float* __restrict__ Wb,
                                 const float* __restrict__ Wc) {
    int i = blockIdx.x * blockDim.x + threadIdx.x;
    if (i < 128 * CH) {
        float v = (i < 64 * CH) ? Wb[i] : Wc[i - 64 * CH];
        fp16 h, l; split2(v, h, l);
        g_Wbch[i] = h; g_Wbcl[i] = l;
    }
}

// ---------------- combine + transpose + split ----------------
__global__ void __launch_bounds__(256) transcomb_kernel(
    const float* __restrict__ x1, const float* __restrict__ x2) {
    __shared__ float t1[32][33], t2[32][33];
    const int b  = blockIdx.z;
    const int n0 = blockIdx.x * 32;
    const int k0 = blockIdx.y * 32;
    const int tx = threadIdx.x, ty = threadIdx.y;
    const float al = g_scal[0], be = g_scal[1];

    const long inb = (long)b * CH * NPIX;
#pragma unroll
    for (int it = 0; it < 4; it++) {
        int ki = ty + it * 8;
        t1[ki][tx] = x1[inb + (long)(k0 + ki) * NPIX + n0 + tx];
        t2[ki][tx] = x2[inb + (long)(k0 + ki) * NPIX + n0 + tx];
    }
    __syncthreads();

#pragma unroll
    for (int it = 0; it < 4; it++) {
        int ni = ty + it * 8;
        float v1 = t1[tx][ni];
        float v2 = t2[tx][ni];
        float vc = al * v1 + be * v2;
        long o1 = ((long)b * NPIX + n0 + ni) * CH + k0 + tx;
        long o2 = ((long)(2 + b) * NPIX + n0 + ni) * CH + k0 + tx;
        long oc = ((long)b * NPIX + n0 + ni) * CH + k0 + tx;
        fp16 h, l;
        split2(v1, h, l); g_xTh[o1] = h; g_xTl[o1] = l;
        split2(v2, h, l); g_xTh[o2] = h; g_xTl[o2] = l;
        split2(vc, h, l); g_xcTh[oc] = h; g_xcTl[oc] = l;
    }
}

// ---------------- fused double-softmax abs-diff -> fp16 hi/lo ----------------
__global__ void __launch_bounds__(256) softdiff_kernel() {
    const long row = blockIdx.x;
    const float* p12 = g_S12 + row * (long)NPIX;
    const float* p21 = g_S21 + row * (long)NPIX;
    fp16* oh = g_Ah + row * (long)NPIX;
    fp16* ol = g_Al + row * (long)NPIX;
    const int t = threadIdx.x;
    constexpr int PER = NPIX / 256;

    float v12[PER], v21[PER];
    float mx12 = -1e30f, mx21 = -1e30f;
#pragma unroll
    for (int i = 0; i < PER; i++) {
        v12[i] = p12[t + i * 256];
        v21[i] = p21[t + i * 256];
        mx12 = fmaxf(mx12, v12[i]);
        mx21 = fmaxf(mx21, v21[i]);
    }
    __shared__ float red[2][8];
#pragma unroll
    for (int o = 16; o > 0; o >>= 1) {
        mx12 = fmaxf(mx12, __shfl_xor_sync(0xffffffffu, mx12, o));
        mx21 = fmaxf(mx21, __shfl_xor_sync(0xffffffffu, mx21, o));
    }
    if ((t & 31) == 0) { red[0][t >> 5] = mx12; red[1][t >> 5] = mx21; }
    __syncthreads();
    mx12 = red[0][0]; mx21 = red[1][0];
#pragma unroll
    for (int w = 1; w < 8; w++) {
        mx12 = fmaxf(mx12, red[0][w]);
        mx21 = fmaxf(mx21, red[1][w]);
    }
    __syncthreads();

    float s12 = 0.0f, s21 = 0.0f;
#pragma unroll
    for (int i = 0; i < PER; i++) {
        v12[i] = __expf(v12[i] - mx12);
        v21[i] = __expf(v21[i] - mx21);
        s12 += v12[i]; s21 += v21[i];
    }
#pragma unroll
    for (int o = 16; o > 0; o >>= 1) {
        s12 += __shfl_xor_sync(0xffffffffu, s12, o);
        s21 += __shfl_xor_sync(0xffffffffu, s21, o);
    }
    if ((t & 31) == 0) { red[0][t >> 5] = s12; red[1][t >> 5] = s21; }
    __syncthreads();
    s12 = red[0][0]; s21 = red[1][0];
#pragma unroll
    for (int w = 1; w < 8; w++) { s12 += red[0][w]; s21 += red[1][w]; }

    const float i12 = 1.0f / s12;
    const float i21 = 1.0f / s21;
#pragma unroll
    for (int i = 0; i < PER; i++) {
        float att = fabsf(v12[i] * i12 - v21[i] * i21);
        fp16 h, l; split2(att, h, l);
        oh[t + i * 256] = h;
        ol[t + i * 256] = l;
    }
}

// ================= shared HMMA helpers =================
__device__ __forceinline__ uint32_t smem_u32(const void* p) {
    uint32_t a;
    asm("{ .reg .u64 t; cvta.to.shared.u64 t, %1; cvt.u32.u64 %0, t; }" : "=r"(a) : "l"(p));
    return a;
}
__device__ __forceinline__ void cp16(uint32_t dst, const void* src) {
    asm volatile("cp.async.cg.shared.global [%0], [%1], 16;" :: "r"(dst), "l"(src));
}
__device__ __forceinline__ void ldsm4(uint32_t* r, uint32_t addr) {
    asm volatile("ldmatrix.sync.aligned.m8n8.x4.shared.b16 {%0,%1,%2,%3}, [%4];"
                 : "=r"(r[0]), "=r"(r[1]), "=r"(r[2]), "=r"(r[3]) : "r"(addr));
}
__device__ __forceinline__ void mma16816(float* d, const uint32_t* a, const uint32_t* b) {
    asm volatile(
        "mma.sync.aligned.m16n8k16.row.col.f32.f16.f16.f32 "
        "{%0,%1,%2,%3}, {%4,%5,%6,%7}, {%8,%9}, {%0,%1,%2,%3};"
        : "+f"(d[0]), "+f"(d[1]), "+f"(d[2]), "+f"(d[3])
        : "r"(a[0]), "r"(a[1]), "r"(a[2]), "r"(a[3]), "r"(b[0]), "r"(b[1]));
}

// ================= hgemm128: 128x128, BK=32, 8 warps (32x64), occ 2 ========
// used for P projection (N=128)
#define ST128_B (2 * 128 * 80)        // A+B stage bytes = 20480
#define SM128   (3 * ST128_B)

template<int BIASMODE, int EPI>
__global__ void __launch_bounds__(256, 2) hgemm128_kernel(
    const fp16* __restrict__ a0, const fp16* __restrict__ a1, const fp16* __restrict__ a2,
    const fp16* __restrict__ b0, const fp16* __restrict__ b1, const fp16* __restrict__ b2,
    int ktPerTerm, int nkt, int lda, int ldb, long bsA, long bsB,
    float* __restrict__ C, fp16* __restrict__ Chi, fp16* __restrict__ Clo,
    int ldc, long bsC, const float* __restrict__ bias)
{
    extern __shared__ __align__(16) fp16 dsm[];
    const int tid = threadIdx.x;
    const int wid = tid >> 5;
    const int lane = tid & 31;
    const int wm = wid >> 1;
    const int wn = wid & 1;
    const int m0 = blockIdx.y * 128;
    const int n0 = blockIdx.x * 128;
    const int z  = blockIdx.z;
    const uint32_t s0 = smem_u32(dsm);

    float acc[2][8][4];
#pragma unroll
    for (int i = 0; i < 2; i++)
#pragma unroll
        for (int j = 0; j < 8; j++)
#pragma unroll
            for (int q = 0; q < 4; q++) acc[i][j][q] = 0.0f;

    const int lrow0 = tid >> 2;
    const int lch0  = tid & 3;
    auto load_tile = [&](int g, int slot) {
        const int t  = g / ktPerTerm;
        const int k0 = (g - t * ktPerTerm) * 32;
        const fp16* Ap = (t == 0 ? a0 : (t == 1 ? a1 : a2)) + z * bsA + (long)m0 * lda + k0;
        const fp16* Bp = (t == 0 ? b0 : (t == 1 ? b1 : b2)) + z * bsB + (long)n0 * ldb + k0;
        const uint32_t da = s0 + slot * ST128_B;
        const uint32_t db = da + 128 * 80;
#pragma unroll
        for (int i = 0; i < 2; i++) {
            int row = lrow0 + i * 64;
            cp16(da + row * 80 + lch0 * 16, Ap + (long)row * lda + lch0 * 8);
            cp16(db + row * 80 + lch0 * 16, Bp + (long)row * ldb + lch0 * 8);
        }
        asm volatile("cp.async.commit_group;");
    };

    load_tile(0, 0);
    if (nkt > 1) load_tile(1, 1);

    int slot = 0;
    for (int g = 0; g < nkt; g++) {
        if (g + 1 < nkt) asm volatile("cp.async.wait_group 1;");
        else             asm volatile("cp.async.wait_group 0;");
        __syncthreads();
        if (g + 2 < nkt) {
            int ns = slot + 2; if (ns >= 3) ns -= 3;
            load_tile(g + 2, ns);
        }
        const uint32_t da = s0 + slot * ST128_B;
        const uint32_t db = da + 128 * 80;
#pragma unroll
        for (int ks = 0; ks < 2; ks++) {
            uint32_t af[2][4];
#pragma unroll
            for (int mt = 0; mt < 2; mt++) {
                int row = wm * 32 + mt * 16 + (lane & 15);
                int kc  = ks * 16 + (lane >> 4) * 8;
                ldsm4(af[mt], da + row * 80 + kc * 2);
            }
            uint32_t bfr[4][4];
#pragma unroll
            for (int p = 0; p < 4; p++) {
                int row = wn * 64 + p * 16 + (lane >> 4) * 8 + (lane & 7);
                int kc  = ks * 16 + ((lane >> 3) & 1) * 8;
                ldsm4(bfr[p], db + row * 80 + kc * 2);
            }
#pragma unroll
            for (int mt = 0; mt < 2; mt++)
#pragma unroll
                for (int p = 0; p < 4; p++) {
                    mma16816(acc[mt][2 * p],     af[mt], &bfr[p][0]);
                    mma16816(acc[mt][2 * p + 1], af[mt], &bfr[p][2]);
                }
        }
        slot++; if (slot >= 3) slot = 0;
        __syncthreads();
    }

#pragma unroll
    for (int mt = 0; mt < 2; mt++) {
        const int mA = m0 + wm * 32 + mt * 16 + (lane >> 2);
        float bvA = 0.0f, bvB = 0.0f;
        if (BIASMODE == 1) { bvA = bias[mA] * g_scal[2]; bvB = bias[mA + 8] * g_scal[2]; }
#pragma unroll
        for (int nt = 0; nt < 8; nt++) {
            const int n = n0 + wn * 64 + nt * 8 + (lane & 3) * 2;
            float c0 = acc[mt][nt][0], c1 = acc[mt][nt][1];
            float c2 = acc[mt][nt][2], c3 = acc[mt][nt][3];
            if (BIASMODE == 1) { c0 += bvA; c1 += bvA; c2 += bvB; c3 += bvB; }
            if (BIASMODE == 2) {
                float b0v = bias[n], b1v = bias[n + 1];
                c0 += b0v; c1 += b1v; c2 += b0v; c3 += b1v;
            }
            if (EPI == 0) {
                float* Cz = C + (long)z * bsC;
                *(float2*)(Cz + (long)mA * ldc + n)       = make_float2(c0, c1);
                *(float2*)(Cz + (long)(mA + 8) * ldc + n) = make_float2(c2, c3);
            } else {
                fp16* Hz = Chi + (long)z * bsC;
                fp16* Lz = Clo + (long)z * bsC;
                fp16 h0, l0, h1, l1, h2, l2, h3, l3;
                split2(c0, h0, l0); split2(c1, h1, l1);
                split2(c2, h2, l2); split2(c3, h3, l3);
                __half2 H0; H0.x = h0; H0.y = h1;
                __half2 H1; H1.x = h2; H1.y = h3;
                __half2 L0; L0.x = l0; L0.y = l1;
                __half2 L1; L1.x = l2; L1.y = l3;
                *(__half2*)(Hz + (long)mA * ldc + n)       = H0;
                *(__half2*)(Hz + (long)(mA + 8) * ldc + n) = H1;
                *(__half2*)(Lz + (long)mA * ldc + n)       = L0;
                *(__half2*)(Lz + (long)(mA + 8) * ldc + n) = L1;
            }
        }
    }
}

// ================= hgemm256: 128x256, BK=32, 8 warps (64x64), occ 1 ========
#define ST256_A (128 * 80)            // 10240
#define ST256_BB (256 * 80)           // 20480
#define ST256_B (ST256_A + ST256_BB)  // 30720
#define SM256   (3 * ST256_B)         // 92160

template<int BIASMODE, int EPI, bool SWAP>
__global__ void __launch_bounds__(256, 1) hgemm256_kernel(
    const fp16* __restrict__ a0, const fp16* __restrict__ a1, const fp16* __restrict__ a2,
    const fp16* __restrict__ b0, const fp16* __restrict__ b1, const fp16* __restrict__ b2,
    int ktPerTerm, int nkt, int lda, int ldb, long bsA, long bsB,
    float* __restrict__ C, fp16* __restrict__ Chi, fp16* __restrict__ Clo,
    int ldc, long bsC, const float* __restrict__ bias)
{
    extern __shared__ __align__(16) fp16 dsm[];
    const int tid = threadIdx.x;
    const int wid = tid >> 5;
    const int lane = tid & 31;
    const int wm = wid >> 2;           // 0..1
    const int wn = wid & 3;            // 0..3
    const int m0 = (SWAP ? blockIdx.x : blockIdx.y) * 128;
    const int n0 = (SWAP ? blockIdx.y : blockIdx.x) * 256;
    const int z  = blockIdx.z;
    const uint32_t s0 = smem_u32(dsm);

    float acc[4][8][4];
#pragma unroll
    for (int i = 0; i < 4; i++)
#pragma unroll
        for (int j = 0; j < 8; j++)
#pragma unroll
            for (int q = 0; q < 4; q++) acc[i][j][q] = 0.0f;

    const int lrow0 = tid >> 2;        // 0..63
    const int lch0  = tid & 3;
    auto load_tile = [&](int g, int slot) {
        const int t  = g / ktPerTerm;
        const int k0 = (g - t * ktPerTerm) * 32;
        const fp16* Ap = (t == 0 ? a0 : (t == 1 ? a1 : a2)) + z * bsA + (long)m0 * lda + k0;
        const fp16* Bp = (t == 0 ? b0 : (t == 1 ? b1 : b2)) + z * bsB + (long)n0 * ldb + k0;
        const uint32_t da = s0 + slot * ST256_B;
        const uint32_t db = da + ST256_A;
#pragma unroll
        for (int i = 0; i < 2; i++) {
            int row = lrow0 + i * 64;
            cp16(da + row * 80 + lch0 * 16, Ap + (long)row * lda + lch0 * 8);
        }
#pragma unroll
        for (int i = 0; i < 4; i++) {
            int row = lrow0 + i * 64;
            cp16(db + row * 80 + lch0 * 16, Bp + (long)row * ldb + lch0 * 8);
        }
        asm volatile("cp.async.commit_group;");
    };

    load_tile(0, 0);
    if (nkt > 1) load_tile(1, 1);

    int slot = 0;
    for (int g = 0; g < nkt; g++) {
        if (g + 1 < nkt) asm volatile("cp.async.wait_group 1;");
        else             asm volatile("cp.async.wait_group 0;");
        __syncthreads();
        if (g + 2 < nkt) {
            int ns = slot + 2; if (ns >= 3) ns -= 3;
            load_tile(g + 2, ns);
        }
        const uint32_t da = s0 + slot * ST256_B;
        const uint32_t db = da + ST256_A;
#pragma unroll
        for (int ks = 0; ks < 2; ks++) {
            uint32_t af[4][4];
#pragma unroll
            for (int mt = 0; mt < 4; mt++) {
                int row = wm * 64 + mt * 16 + (lane & 15);
                int kc  = ks * 16 + (lane >> 4) * 8;
                ldsm4(af[mt], da + row * 80 + kc * 2);
            }
            uint32_t bfr[4][4];
#pragma unroll
            for (int p = 0; p < 4; p++) {
                int row = wn * 64 + p * 16 + (lane >> 4) * 8 + (lane & 7);
                int kc  = ks * 16 + ((lane >> 3) & 1) * 8;
                ldsm4(bfr[p], db + row * 80 + kc * 2);
            }
#pragma unroll
            for (int mt = 0; mt < 4; mt++)
#pragma unroll
                for (int p = 0; p < 4; p++) {
                    mma16816(acc[mt][2 * p],     af[mt], &bfr[p][0]);
                    mma16816(acc[mt][2 * p + 1], af[mt], &bfr[p][2]);
                }
        }
        slot++; if (slot >= 3) slot = 0;
        __syncthreads();
    }

#pragma unroll
    for (int mt = 0; mt < 4; mt++) {
        const int mA = m0 + wm * 64 + mt * 16 + (lane >> 2);
        float bvA = 0.0f, bvB = 0.0f;
        if (BIASMODE == 1) { bvA = bias[mA] * g_scal[2]; bvB = bias[mA + 8] * g_scal[2]; }
#pragma unroll
        for (int nt = 0; nt < 8; nt++) {
            const int n = n0 + wn * 64 + nt * 8 + (lane & 3) * 2;
            float c0 = acc[mt][nt][0], c1 = acc[mt][nt][1];
            float c2 = acc[mt][nt][2], c3 = acc[mt][nt][3];
            if (BIASMODE == 1) { c0 += bvA; c1 += bvA; c2 += bvB; c3 += bvB; }
            if (EPI == 0) {
                float* Cz = C + (long)z * bsC;
                *(float2*)(Cz + (long)mA * ldc + n)       = make_float2(c0, c1);
                *(float2*)(Cz + (long)(mA + 8) * ldc + n) = make_float2(c2, c3);
            } else {
                fp16* Hz = Chi + (long)z * bsC;
                fp16* Lz = Clo + (long)z * bsC;
                fp16 h0, l0, h1, l1, h2, l2, h3, l3;
                split2(c0, h0, l0); split2(c1, h1, l1);
                split2(c2, h2, l2); split2(c3, h3, l3);
                __half2 H0; H0.x = h0; H0.y = h1;
                __half2 H1; H1.x = h2; H1.y = h3;
                __half2 L0; L0.x = l0; L0.y = l1;
                __half2 L1; L1.x = l2; L1.y = l3;
                *(__half2*)(Hz + (long)mA * ldc + n)       = H0;
                *(__half2*)(Hz + (long)(mA + 8) * ldc + n) = H1;
                *(__half2*)(Lz + (long)mA * ldc + n)       = L0;
                *(__half2*)(Lz + (long)(mA + 8) * ldc + n) = L1;
            }
        }
    }
}

// ---------------- launch ----------------
extern "C" void kernel_launch(void* const* d_in, const int* in_sizes, int n_in,
                              void* d_out, int out_size) {
    const float* x1    = (const float*)d_in[0];
    const float* x2    = (const float*)d_in[1];
    const float* Wb    = (const float*)d_in[2];
    const float* bb    = (const float*)d_in[3];
    const float* Wc    = (const float*)d_in[4];
    const float* bc    = (const float*)d_in[5];
    const float* Wdd   = (const float*)d_in[6];
    const float* bd    = (const float*)d_in[7];
    const float* alpha = (const float*)d_in[8];
    const float* beta  = (const float*)d_in[9];
    float* out = (float*)d_out;

    fp16 *xTh, *xTl, *xcTh, *xcTl, *Wbch, *Wbcl, *Wdh, *Wdl, *Ph, *Pl, *Fh, *Fl, *Ah, *Al;
    float *S12, *S21, *bias2;
    cudaGetSymbolAddress((void**)&xTh,  g_xTh);
    cudaGetSymbolAddress((void**)&xTl,  g_xTl);
    cudaGetSymbolAddress((void**)&xcTh, g_xcTh);
    cudaGetSymbolAddress((void**)&xcTl, g_xcTl);
    cudaGetSymbolAddress((void**)&Wbch, g_Wbch);
    cudaGetSymbolAddress((void**)&Wbcl, g_Wbcl);
    cudaGetSymbolAddress((void**)&Wdh,  g_Wdh);
    cudaGetSymbolAddress((void**)&Wdl,  g_Wdl);
    cudaGetSymbolAddress((void**)&Ph,   g_Ph);
    cudaGetSymbolAddress((void**)&Pl,   g_Pl);
    cudaGetSymbolAddress((void**)&Fh,   g_Fh);
    cudaGetSymbolAddress((void**)&Fl,   g_Fl);
    cudaGetSymbolAddress((void**)&S12,  g_S12);
    cudaGetSymbolAddress((void**)&S21,  g_S21);
    cudaGetSymbolAddress((void**)&Ah,   g_Ah);
    cudaGetSymbolAddress((void**)&Al,   g_Al);
    cudaGetSymbolAddress((void**)&bias2, g_bias2);

    cudaFuncSetAttribute(hgemm128_kernel<2, 1>,
                         cudaFuncAttributeMaxDynamicSharedMemorySize, SM128);
    cudaFuncSetAttribute(hgemm256_kernel<1, 1, false>,
                         cudaFuncAttributeMaxDynamicSharedMemorySize, SM256);
    cudaFuncSetAttribute(hgemm256_kernel<0, 0, false>,
                         cudaFuncAttributeMaxDynamicSharedMemorySize, SM256);
    cudaFuncSetAttribute(hgemm256_kernel<0, 0, true>,
                         cudaFuncAttributeMaxDynamicSharedMemorySize, SM256);

    prep_kernel<<<1, 128>>>(bb, bc, alpha, beta);

    dim3 gT(NPIX / 32, CH / 32, BATCH);
    transcomb_kernel<<<gT, dim3(32, 8)>>>(x1, x2);

    wbc_split_kernel<<<(128 * CH + 255) / 256, 256>>>(Wb, Wc);
    split_kernel<<<(CH * CH + 255) / 256, 256>>>(Wdd, Wdh, Wdl, CH * CH);

    const long bsXT = (long)NPIX * CH;
    const long bsP  = (long)NPIX * 128;
    const long bsF  = (long)CH * NPIX;
    const long bsS  = (long)NPIX * NPIX;

    // P^T = x^T @ Wbc^T  (M=4096, N=128, K=512), bias per-col, fp16 epi
    hgemm128_kernel<2, 1><<<dim3(1, NPIX / 128, 4), 256, SM128>>>(
        xTh, xTl, xTh,  Wbch, Wbch, Wbcl,
        CH / 32, 3 * CH / 32, CH, CH, bsXT, 0L,
        nullptr, Ph, Pl, 128, bsP, bias2);

    // F = Wdd @ xc + (a+b)*bd  (M=512, N=4096, K=512), fp16 epi
    hgemm256_kernel<1, 1, false><<<dim3(NPIX / 256, CH / 128, BATCH), 256, SM256>>>(
        Wdh, Wdl, Wdh,  xcTh, xcTh, xcTl,
        CH / 32, 3 * CH / 32, CH, CH, 0L, bsXT,
        nullptr, Fh, Fl, NPIX, bsF, bd);

    // logits S12[n,m] = A1[n,:]·B2[m,:]  (M=N=4096, K=64, 3 terms)
    dim3 gS(NPIX / 256, NPIX / 128, BATCH);
    hgemm256_kernel<0, 0, false><<<gS, 256, SM256>>>(
        Ph, Pl, Ph,  Ph + 2 * bsP + 64, Ph + 2 * bsP + 64, Pl + 2 * bsP + 64,
        2, 6, 128, 128, bsP, bsP,
        S12, nullptr, nullptr, NPIX, bsS, nullptr);
    hgemm256_kernel<0, 0, false><<<gS, 256, SM256>>>(
        Ph + 2 * bsP, Pl + 2 * bsP, Ph + 2 * bsP,  Ph + 64, Ph + 64, Pl + 64,
        2, 6, 128, 128, bsP, bsP,
        S21, nullptr, nullptr, NPIX, bsS, nullptr);

    // att = |softmax(S12)-softmax(S21)| -> fp16 hi/lo
    softdiff_kernel<<<BATCH * NPIX, 256>>>();

    // out[c,n] = sum_m F[c,m]*att[n,m]  (M=512, N=4096, K=3*4096)
    // SWAP: x walks c-blocks so att tiles are L2-shared by the 4 consumers
    hgemm256_kernel<0, 0, true><<<dim3(CH / 128, NPIX / 256, BATCH), 256, SM256>>>(
        Fh, Fl, Fh,  Ah, Ah, Al,
        NPIX / 32, 3 * NPIX / 32, NPIX, NPIX, bsF, bsS,
        out, nullptr, nullptr, NPIX, bsF, nullptr);
}

// round 7
// speedup vs baseline: 1.2522x; 1.2522x over previous
#include <cuda_runtime.h>
#include <cuda_fp16.h>
#include <math.h>
#include <stdint.h>

#define BATCH 2
#define CH    512
#define CQ    64
#define NPIX  4096

typedef __half fp16;

// ---------------- static scratch ----------------
__device__ __align__(128) fp16  g_xTh[4L * NPIX * CH];   // [which*2+b][n][c] hi
__device__ __align__(128) fp16  g_xTl[4L * NPIX * CH];
__device__ __align__(128) fp16  g_xcTh[2L * NPIX * CH];  // [b][n][c]
__device__ __align__(128) fp16  g_xcTl[2L * NPIX * CH];
__device__ __align__(128) fp16  g_Wbch[128 * CH];        // [o(128)][c] (Wb;Wc)
__device__ __align__(128) fp16  g_Wbcl[128 * CH];
__device__ __align__(128) fp16  g_Wdh[CH * CH];
__device__ __align__(128) fp16  g_Wdl[CH * CH];
__device__ __align__(128) fp16  g_Ph[4L * NPIX * 128];   // [which*2+b][n][o]
__device__ __align__(128) fp16  g_Pl[4L * NPIX * 128];
__device__ __align__(128) fp16  g_Fh[(long)BATCH * CH * NPIX];  // [b][c][n]
__device__ __align__(128) fp16  g_Fl[(long)BATCH * CH * NPIX];
__device__ __align__(128) float g_S12[(size_t)BATCH * NPIX * NPIX];
__device__ __align__(128) float g_S21[(size_t)BATCH * NPIX * NPIX];
__device__ __align__(128) fp16  g_Ah[(size_t)BATCH * NPIX * NPIX];
__device__ __align__(128) fp16  g_Al[(size_t)BATCH * NPIX * NPIX];
__device__ float g_scal[4];
__device__ float g_bias2[128];

__device__ __forceinline__ void split2(float v, fp16& h, fp16& l) {
    h = __float2half_rn(v);
    l = __float2half_rn(v - __half2float(h));
}

// ---------------- prep ----------------
__global__ void prep_kernel(const float* bb, const float* bc,
                            const float* a, const float* b) {
    int t = threadIdx.x;
    if (t < 64)       g_bias2[t] = bb[t];
    else if (t < 128) g_bias2[t] = bc[t - 64];
    if (t == 0) { g_scal[0] = a[0]; g_scal[1] = b[0]; g_scal[2] = a[0] + b[0]; }
}

__global__ void split_kernel(const float* __restrict__ src,
                             fp16* __restrict__ hi, fp16* __restrict__ lo, int n) {
    int i = blockIdx.x * blockDim.x + threadIdx.x;
    if (i < n) { fp16 h, l; split2(src[i], h, l); hi[i] = h; lo[i] = l; }
}

__global__ void wbc_split_kernel(const float* __restrict__ Wb,
                                 const float* __restrict__ Wc) {
    int i = blockIdx.x * blockDim.x + threadIdx.x;
    if (i < 128 * CH) {
        float v = (i < 64 * CH) ? Wb[i] : Wc[i - 64 * CH];
        fp16 h, l; split2(v, h, l);
        g_Wbch[i] = h; g_Wbcl[i] = l;
    }
}

// ---------------- combine + transpose + split ----------------
__global__ void __launch_bounds__(256) transcomb_kernel(
    const float* __restrict__ x1, const float* __restrict__ x2) {
    __shared__ float t1[32][33], t2[32][33];
    const int b  = blockIdx.z;
    const int n0 = blockIdx.x * 32;
    const int k0 = blockIdx.y * 32;
    const int tx = threadIdx.x, ty = threadIdx.y;
    const float al = g_scal[0], be = g_scal[1];

    const long inb = (long)b * CH * NPIX;
#pragma unroll
    for (int it = 0; it < 4; it++) {
        int ki = ty + it * 8;
        t1[ki][tx] = x1[inb + (long)(k0 + ki) * NPIX + n0 + tx];
        t2[ki][tx] = x2[inb + (long)(k0 + ki) * NPIX + n0 + tx];
    }
    __syncthreads();

#pragma unroll
    for (int it = 0; it < 4; it++) {
        int ni = ty + it * 8;
        float v1 = t1[tx][ni];
        float v2 = t2[tx][ni];
        float vc = al * v1 + be * v2;
        long o1 = ((long)b * NPIX + n0 + ni) * CH + k0 + tx;
        long o2 = ((long)(2 + b) * NPIX + n0 + ni) * CH + k0 + tx;
        long oc = ((long)b * NPIX + n0 + ni) * CH + k0 + tx;
        fp16 h, l;
        split2(v1, h, l); g_xTh[o1] = h; g_xTl[o1] = l;
        split2(v2, h, l); g_xTh[o2] = h; g_xTl[o2] = l;
        split2(vc, h, l); g_xcTh[oc] = h; g_xcTl[oc] = l;
    }
}

// ---------------- fused double-softmax abs-diff -> fp16 hi/lo ----------------
__global__ void __launch_bounds__(256) softdiff_kernel() {
    const long row = blockIdx.x;
    const float* p12 = g_S12 + row * (long)NPIX;
    const float* p21 = g_S21 + row * (long)NPIX;
    fp16* oh = g_Ah + row * (long)NPIX;
    fp16* ol = g_Al + row * (long)NPIX;
    const int t = threadIdx.x;
    constexpr int PER = NPIX / 256;

    float v12[PER], v21[PER];
    float mx12 = -1e30f, mx21 = -1e30f;
#pragma unroll
    for (int i = 0; i < PER; i++) {
        v12[i] = p12[t + i * 256];
        v21[i] = p21[t + i * 256];
        mx12 = fmaxf(mx12, v12[i]);
        mx21 = fmaxf(mx21, v21[i]);
    }
    __shared__ float red[2][8];
#pragma unroll
    for (int o = 16; o > 0; o >>= 1) {
        mx12 = fmaxf(mx12, __shfl_xor_sync(0xffffffffu, mx12, o));
        mx21 = fmaxf(mx21, __shfl_xor_sync(0xffffffffu, mx21, o));
    }
    if ((t & 31) == 0) { red[0][t >> 5] = mx12; red[1][t >> 5] = mx21; }
    __syncthreads();
    mx12 = red[0][0]; mx21 = red[1][0];
#pragma unroll
    for (int w = 1; w < 8; w++) {
        mx12 = fmaxf(mx12, red[0][w]);
        mx21 = fmaxf(mx21, red[1][w]);
    }
    __syncthreads();

    float s12 = 0.0f, s21 = 0.0f;
#pragma unroll
    for (int i = 0; i < PER; i++) {
        v12[i] = __expf(v12[i] - mx12);
        v21[i] = __expf(v21[i] - mx21);
        s12 += v12[i]; s21 += v21[i];
    }
#pragma unroll
    for (int o = 16; o > 0; o >>= 1) {
        s12 += __shfl_xor_sync(0xffffffffu, s12, o);
        s21 += __shfl_xor_sync(0xffffffffu, s21, o);
    }
    if ((t & 31) == 0) { red[0][t >> 5] = s12; red[1][t >> 5] = s21; }
    __syncthreads();
    s12 = red[0][0]; s21 = red[1][0];
#pragma unroll
    for (int w = 1; w < 8; w++) { s12 += red[0][w]; s21 += red[1][w]; }

    const float i12 = 1.0f / s12;
    const float i21 = 1.0f / s21;
#pragma unroll
    for (int i = 0; i < PER; i++) {
        float att = fabsf(v12[i] * i12 - v21[i] * i21);
        fp16 h, l; split2(att, h, l);
        oh[t + i * 256] = h;
        ol[t + i * 256] = l;
    }
}

// ================= HMMA fp16 multi-term GEMM, 3-stage cp.async =============
// C[m,n] = sum over tiles of A_t[m,k] * B_t[n,k]   (A, B K-major fp16)
// BM=BN=128, BK=32, 8 warps (4M x 2N, 32x64 warp tile), occ 2.
// Tile order is TERM-INNER: g -> (k = g/3, term = g%3) so the shared-operand
// second use is 1 iteration later (L2-hot).
// BIASMODE: 0 none, 1 per-row bias[m]*g_scal[2], 2 per-col bias[n].
// EPI: 0 fp32 C, 1 fp16 hi/lo pair. SWAP: m from blockIdx.x.

#define STAGE_B (2 * 128 * 80)        // A+B bytes per stage = 20480
#define SMEM_DYN (3 * STAGE_B)        // 61440

__device__ __forceinline__ uint32_t smem_u32(const void* p) {
    uint32_t a;
    asm("{ .reg .u64 t; cvta.to.shared.u64 t, %1; cvt.u32.u64 %0, t; }" : "=r"(a) : "l"(p));
    return a;
}
__device__ __forceinline__ void cp16(uint32_t dst, const void* src) {
    asm volatile("cp.async.cg.shared.global [%0], [%1], 16;" :: "r"(dst), "l"(src));
}
__device__ __forceinline__ void ldsm4(uint32_t* r, uint32_t addr) {
    asm volatile("ldmatrix.sync.aligned.m8n8.x4.shared.b16 {%0,%1,%2,%3}, [%4];"
                 : "=r"(r[0]), "=r"(r[1]), "=r"(r[2]), "=r"(r[3]) : "r"(addr));
}
__device__ __forceinline__ void mma16816(float* d, const uint32_t* a, const uint32_t* b) {
    asm volatile(
        "mma.sync.aligned.m16n8k16.row.col.f32.f16.f16.f32 "
        "{%0,%1,%2,%3}, {%4,%5,%6,%7}, {%8,%9}, {%0,%1,%2,%3};"
        : "+f"(d[0]), "+f"(d[1]), "+f"(d[2]), "+f"(d[3])
        : "r"(a[0]), "r"(a[1]), "r"(a[2]), "r"(a[3]), "r"(b[0]), "r"(b[1]));
}

template<int BIASMODE, int EPI, bool SWAP>
__global__ void __launch_bounds__(256, 2) hgemm_kernel(
    const fp16* __restrict__ a0, const fp16* __restrict__ a1, const fp16* __restrict__ a2,
    const fp16* __restrict__ b0, const fp16* __restrict__ b1, const fp16* __restrict__ b2,
    int nkt, int lda, int ldb, long bsA, long bsB,
    float* __restrict__ C, fp16* __restrict__ Chi, fp16* __restrict__ Clo,
    int ldc, long bsC, const float* __restrict__ bias)
{
    extern __shared__ __align__(16) fp16 dsm[];

    const int tid = threadIdx.x;
    const int wid = tid >> 5;
    const int lane = tid & 31;
    const int wm = wid >> 1;
    const int wn = wid & 1;
    const int m0 = (SWAP ? blockIdx.x : blockIdx.y) * 128;
    const int n0 = (SWAP ? blockIdx.y : blockIdx.x) * 128;
    const int z  = blockIdx.z;

    const uint32_t s0 = smem_u32(dsm);

    float acc[2][8][4];
#pragma unroll
    for (int i = 0; i < 2; i++)
#pragma unroll
        for (int j = 0; j < 8; j++)
#pragma unroll
            for (int q = 0; q < 4; q++) acc[i][j][q] = 0.0f;

    const int lrow0 = tid >> 2;
    const int lch0  = tid & 3;
    // TERM-INNER mapping: g -> (k-tile g/3, term g%3)
    auto load_tile = [&](int g, int slot) {
        const int t  = g % 3;
        const int k0 = (g / 3) * 32;
        const fp16* Ap = (t == 0 ? a0 : (t == 1 ? a1 : a2)) + z * bsA + (long)m0 * lda + k0;
        const fp16* Bp = (t == 0 ? b0 : (t == 1 ? b1 : b2)) + z * bsB + (long)n0 * ldb + k0;
        const uint32_t da = s0 + slot * STAGE_B;
        const uint32_t db = da + 128 * 80;
#pragma unroll
        for (int i = 0; i < 2; i++) {
            int row = lrow0 + i * 64;
            cp16(da + row * 80 + lch0 * 16, Ap + (long)row * lda + lch0 * 8);
            cp16(db + row * 80 + lch0 * 16, Bp + (long)row * ldb + lch0 * 8);
        }
        asm volatile("cp.async.commit_group;");
    };

    load_tile(0, 0);
    if (nkt > 1) load_tile(1, 1);

    int slot = 0;
    for (int g = 0; g < nkt; g++) {
        if (g + 1 < nkt) asm volatile("cp.async.wait_group 1;");
        else             asm volatile("cp.async.wait_group 0;");
        __syncthreads();

        if (g + 2 < nkt) {
            int ns = slot + 2; if (ns >= 3) ns -= 3;
            load_tile(g + 2, ns);
        }

        const uint32_t da = s0 + slot * STAGE_B;
        const uint32_t db = da + 128 * 80;
#pragma unroll
        for (int ks = 0; ks < 2; ks++) {
            uint32_t af[2][4];
#pragma unroll
            for (int mt = 0; mt < 2; mt++) {
                int row = wm * 32 + mt * 16 + (lane & 15);
                int kc  = ks * 16 + (lane >> 4) * 8;
                ldsm4(af[mt], da + row * 80 + kc * 2);
            }
            uint32_t bfr[4][4];
#pragma unroll
            for (int p = 0; p < 4; p++) {
                int row = wn * 64 + p * 16 + (lane >> 4) * 8 + (lane & 7);
                int kc  = ks * 16 + ((lane >> 3) & 1) * 8;
                ldsm4(bfr[p], db + row * 80 + kc * 2);
            }
#pragma unroll
            for (int mt = 0; mt < 2; mt++)
#pragma unroll
                for (int p = 0; p < 4; p++) {
                    mma16816(acc[mt][2 * p],     af[mt], &bfr[p][0]);
                    mma16816(acc[mt][2 * p + 1], af[mt], &bfr[p][2]);
                }
        }
        slot++; if (slot >= 3) slot = 0;
        __syncthreads();
    }

    // epilogue
#pragma unroll
    for (int mt = 0; mt < 2; mt++) {
        const int mA = m0 + wm * 32 + mt * 16 + (lane >> 2);
        float bvA = 0.0f, bvB = 0.0f;
        if (BIASMODE == 1) { bvA = bias[mA] * g_scal[2]; bvB = bias[mA + 8] * g_scal[2]; }
#pragma unroll
        for (int nt = 0; nt < 8; nt++) {
            const int n = n0 + wn * 64 + nt * 8 + (lane & 3) * 2;
            float c0 = acc[mt][nt][0], c1 = acc[mt][nt][1];
            float c2 = acc[mt][nt][2], c3 = acc[mt][nt][3];
            if (BIASMODE == 1) { c0 += bvA; c1 += bvA; c2 += bvB; c3 += bvB; }
            if (BIASMODE == 2) {
                float b0v = bias[n], b1v = bias[n + 1];
                c0 += b0v; c1 += b1v; c2 += b0v; c3 += b1v;
            }
            if (EPI == 0) {
                float* Cz = C + (long)z * bsC;
                *(float2*)(Cz + (long)mA * ldc + n)       = make_float2(c0, c1);
                *(float2*)(Cz + (long)(mA + 8) * ldc + n) = make_float2(c2, c3);
            } else {
                fp16* Hz = Chi + (long)z * bsC;
                fp16* Lz = Clo + (long)z * bsC;
                fp16 h0, l0, h1, l1, h2, l2, h3, l3;
                split2(c0, h0, l0); split2(c1, h1, l1);
                split2(c2, h2, l2); split2(c3, h3, l3);
                __half2 H0; H0.x = h0; H0.y = h1;
                __half2 H1; H1.x = h2; H1.y = h3;
                __half2 L0; L0.x = l0; L0.y = l1;
                __half2 L1; L1.x = l2; L1.y = l3;
                *(__half2*)(Hz + (long)mA * ldc + n)       = H0;
                *(__half2*)(Hz + (long)(mA + 8) * ldc + n) = H1;
                *(__half2*)(Lz + (long)mA * ldc + n)       = L0;
                *(__half2*)(Lz + (long)(mA + 8) * ldc + n) = L1;
            }
        }
    }
}

// ---------------- launch ----------------
extern "C" void kernel_launch(void* const* d_in, const int* in_sizes, int n_in,
                              void* d_out, int out_size) {
    const float* x1    = (const float*)d_in[0];
    const float* x2    = (const float*)d_in[1];
    const float* Wb    = (const float*)d_in[2];
    const float* bb    = (const float*)d_in[3];
    const float* Wc    = (const float*)d_in[4];
    const float* bc    = (const float*)d_in[5];
    const float* Wdd   = (const float*)d_in[6];
    const float* bd    = (const float*)d_in[7];
    const float* alpha = (const float*)d_in[8];
    const float* beta  = (const float*)d_in[9];
    float* out = (float*)d_out;

    fp16 *xTh, *xTl, *xcTh, *xcTl, *Wbch, *Wbcl, *Wdh, *Wdl, *Ph, *Pl, *Fh, *Fl, *Ah, *Al;
    float *S12, *S21, *bias2;
    cudaGetSymbolAddress((void**)&xTh,  g_xTh);
    cudaGetSymbolAddress((void**)&xTl,  g_xTl);
    cudaGetSymbolAddress((void**)&xcTh, g_xcTh);
    cudaGetSymbolAddress((void**)&xcTl, g_xcTl);
    cudaGetSymbolAddress((void**)&Wbch, g_Wbch);
    cudaGetSymbolAddress((void**)&Wbcl, g_Wbcl);
    cudaGetSymbolAddress((void**)&Wdh,  g_Wdh);
    cudaGetSymbolAddress((void**)&Wdl,  g_Wdl);
    cudaGetSymbolAddress((void**)&Ph,   g_Ph);
    cudaGetSymbolAddress((void**)&Pl,   g_Pl);
    cudaGetSymbolAddress((void**)&Fh,   g_Fh);
    cudaGetSymbolAddress((void**)&Fl,   g_Fl);
    cudaGetSymbolAddress((void**)&S12,  g_S12);
    cudaGetSymbolAddress((void**)&S21,  g_S21);
    cudaGetSymbolAddress((void**)&Ah,   g_Ah);
    cudaGetSymbolAddress((void**)&Al,   g_Al);
    cudaGetSymbolAddress((void**)&bias2, g_bias2);

    cudaFuncSetAttribute(hgemm_kernel<2, 1, false>,
                         cudaFuncAttributeMaxDynamicSharedMemorySize, SMEM_DYN);
    cudaFuncSetAttribute(hgemm_kernel<1, 1, false>,
                         cudaFuncAttributeMaxDynamicSharedMemorySize, SMEM_DYN);
    cudaFuncSetAttribute(hgemm_kernel<0, 0, false>,
                         cudaFuncAttributeMaxDynamicSharedMemorySize, SMEM_DYN);
    cudaFuncSetAttribute(hgemm_kernel<0, 0, true>,
                         cudaFuncAttributeMaxDynamicSharedMemorySize, SMEM_DYN);

    prep_kernel<<<1, 128>>>(bb, bc, alpha, beta);

    dim3 gT(NPIX / 32, CH / 32, BATCH);
    transcomb_kernel<<<gT, dim3(32, 8)>>>(x1, x2);

    wbc_split_kernel<<<(128 * CH + 255) / 256, 256>>>(Wb, Wc);
    split_kernel<<<(CH * CH + 255) / 256, 256>>>(Wdd, Wdh, Wdl, CH * CH);

    const long bsXT = (long)NPIX * CH;
    const long bsP  = (long)NPIX * 128;
    const long bsF  = (long)CH * NPIX;
    const long bsS  = (long)NPIX * NPIX;

    // P^T = x^T @ Wbc^T (M=4096, N=128, K=512), bias per-col, fp16 epi
    // terms: (xh,Wh), (xl,Wh), (xh,Wl)
    hgemm_kernel<2, 1, false><<<dim3(1, NPIX / 128, 4), 256, SMEM_DYN>>>(
        xTh, xTl, xTh,  Wbch, Wbch, Wbcl,
        3 * CH / 32, CH, CH, bsXT, 0L,
        nullptr, Ph, Pl, 128, bsP, bias2);

    // F = Wdd @ xc + (a+b)*bd (M=512, N=4096, K=512), bias per-row, fp16 epi
    hgemm_kernel<1, 1, false><<<dim3(NPIX / 128, CH / 128, BATCH), 256, SMEM_DYN>>>(
        Wdh, Wdl, Wdh,  xcTh, xcTh, xcTl,
        3 * CH / 32, CH, CH, 0L, bsXT,
        nullptr, Fh, Fl, NPIX, bsF, bd);

    // logits S12[n,m] = A1[n,:]·B2[m,:]  (M=N=4096, K=64)
    dim3 gS(NPIX / 128, NPIX / 128, BATCH);
    hgemm_kernel<0, 0, false><<<gS, 256, SMEM_DYN>>>(
        Ph, Pl, Ph,  Ph + 2 * bsP + 64, Ph + 2 * bsP + 64, Pl + 2 * bsP + 64,
        6, 128, 128, bsP, bsP,
        S12, nullptr, nullptr, NPIX, bsS, nullptr);
    hgemm_kernel<0, 0, false><<<gS, 256, SMEM_DYN>>>(
        Ph + 2 * bsP, Pl + 2 * bsP, Ph + 2 * bsP,  Ph + 64, Ph + 64, Pl + 64,
        6, 128, 128, bsP, bsP,
        S21, nullptr, nullptr, NPIX, bsS, nullptr);

    // att = |softmax(S12)-softmax(S21)| -> fp16 hi/lo
    softdiff_kernel<<<BATCH * NPIX, 256>>>();

    // out[c,n] = sum_m F[c,m]*att[n,m]  (M=512, N=4096, K=3*4096 tiles)
    // SWAP: x walks c-blocks so att tiles are L2-shared by the 4 consumers.
    // term-inner: Ah(k) reused 1 iteration apart (terms 0,1), Al in term 2.
    hgemm_kernel<0, 0, true><<<dim3(CH / 128, NPIX / 128, BATCH), 256, SMEM_DYN>>>(
        Fh, Fl, Fh,  Ah, Ah, Al,
        3 * NPIX / 32, NPIX, NPIX, bsF, bsS,
        out, nullptr, nullptr, NPIX, bsF, nullptr);
}

// round 8
// speedup vs baseline: 1.5270x; 1.2195x over previous
#include <cuda_runtime.h>
#include <cuda_fp16.h>
#include <math.h>
#include <stdint.h>

#define BATCH 2
#define CH    512
#define CQ    64
#define NPIX  4096

typedef __half fp16;

// ---------------- static scratch ----------------
__device__ __align__(128) fp16  g_xTh[4L * NPIX * CH];   // [which*2+b][n][c] hi
__device__ __align__(128) fp16  g_xTl[4L * NPIX * CH];
__device__ __align__(128) fp16  g_xcTh[2L * NPIX * CH];  // [b][n][c]
__device__ __align__(128) fp16  g_xcTl[2L * NPIX * CH];
__device__ __align__(128) fp16  g_Wbch[128 * CH];        // [o(128)][c] (Wb;Wc)
__device__ __align__(128) fp16  g_Wbcl[128 * CH];
__device__ __align__(128) fp16  g_Wdh[CH * CH];
__device__ __align__(128) fp16  g_Wdl[CH * CH];
__device__ __align__(128) fp16  g_Ph[4L * NPIX * 128];   // [which*2+b][n][o]
__device__ __align__(128) fp16  g_Pl[4L * NPIX * 128];
__device__ __align__(128) fp16  g_Fh[(long)BATCH * CH * NPIX];  // [b][c][n]
__device__ __align__(128) fp16  g_Fl[(long)BATCH * CH * NPIX];
__device__ __align__(128) float g_S12[(size_t)BATCH * NPIX * NPIX];
__device__ __align__(128) float g_S21[(size_t)BATCH * NPIX * NPIX];
__device__ __align__(128) fp16  g_Ah[(size_t)BATCH * NPIX * NPIX];
__device__ float g_scal[4];
__device__ float g_bias2[128];

__device__ __forceinline__ void split2(float v, fp16& h, fp16& l) {
    h = __float2half_rn(v);
    l = __float2half_rn(v - __half2float(h));
}

// ---------------- prep ----------------
__global__ void prep_kernel(const float* bb, const float* bc,
                            const float* a, const float* b) {
    int t = threadIdx.x;
    if (t < 64)       g_bias2[t] = bb[t];
    else if (t < 128) g_bias2[t] = bc[t - 64];
    if (t == 0) { g_scal[0] = a[0]; g_scal[1] = b[0]; g_scal[2] = a[0] + b[0]; }
}

__global__ void split_kernel(const float* __restrict__ src,
                             fp16* __restrict__ hi, fp16* __restrict__ lo, int n) {
    int i = blockIdx.x * blockDim.x + threadIdx.x;
    if (i < n) { fp16 h, l; split2(src[i], h, l); hi[i] = h; lo[i] = l; }
}

__global__ void wbc_split_kernel(const float* __restrict__ Wb,
                                 const float* __restrict__ Wc) {
    int i = blockIdx.x * blockDim.x + threadIdx.x;
    if (i < 128 * CH) {
        float v = (i < 64 * CH) ? Wb[i] : Wc[i - 64 * CH];
        fp16 h, l; split2(v, h, l);
        g_Wbch[i] = h; g_Wbcl[i] = l;
    }
}

// ---------------- combine + transpose + split ----------------
__global__ void __launch_bounds__(256) transcomb_kernel(
    const float* __restrict__ x1, const float* __restrict__ x2) {
    __shared__ float t1[32][33], t2[32][33];
    const int b  = blockIdx.z;
    const int n0 = blockIdx.x * 32;
    const int k0 = blockIdx.y * 32;
    const int tx = threadIdx.x, ty = threadIdx.y;
    const float al = g_scal[0], be = g_scal[1];

    const long inb = (long)b * CH * NPIX;
#pragma unroll
    for (int it = 0; it < 4; it++) {
        int ki = ty + it * 8;
        t1[ki][tx] = x1[inb + (long)(k0 + ki) * NPIX + n0 + tx];
        t2[ki][tx] = x2[inb + (long)(k0 + ki) * NPIX + n0 + tx];
    }
    __syncthreads();

#pragma unroll
    for (int it = 0; it < 4; it++) {
        int ni = ty + it * 8;
        float v1 = t1[tx][ni];
        float v2 = t2[tx][ni];
        float vc = al * v1 + be * v2;
        long o1 = ((long)b * NPIX + n0 + ni) * CH + k0 + tx;
        long o2 = ((long)(2 + b) * NPIX + n0 + ni) * CH + k0 + tx;
        long oc = ((long)b * NPIX + n0 + ni) * CH + k0 + tx;
        fp16 h, l;
        split2(v1, h, l); g_xTh[o1] = h; g_xTl[o1] = l;
        split2(v2, h, l); g_xTh[o2] = h; g_xTl[o2] = l;
        split2(vc, h, l); g_xcTh[oc] = h; g_xcTl[oc] = l;
    }
}

// ---------------- fused double-softmax abs-diff -> fp16 (hi only) ----------
__global__ void __launch_bounds__(256) softdiff_kernel() {
    const long row = blockIdx.x;
    const float* p12 = g_S12 + row * (long)NPIX;
    const float* p21 = g_S21 + row * (long)NPIX;
    fp16* oh = g_Ah + row * (long)NPIX;
    const int t = threadIdx.x;
    constexpr int PER = NPIX / 256;

    float v12[PER], v21[PER];
    float mx12 = -1e30f, mx21 = -1e30f;
#pragma unroll
    for (int i = 0; i < PER; i++) {
        v12[i] = p12[t + i * 256];
        v21[i] = p21[t + i * 256];
        mx12 = fmaxf(mx12, v12[i]);
        mx21 = fmaxf(mx21, v21[i]);
    }
    __shared__ float red[2][8];
#pragma unroll
    for (int o = 16; o > 0; o >>= 1) {
        mx12 = fmaxf(mx12, __shfl_xor_sync(0xffffffffu, mx12, o));
        mx21 = fmaxf(mx21, __shfl_xor_sync(0xffffffffu, mx21, o));
    }
    if ((t & 31) == 0) { red[0][t >> 5] = mx12; red[1][t >> 5] = mx21; }
    __syncthreads();
    mx12 = red[0][0]; mx21 = red[1][0];
#pragma unroll
    for (int w = 1; w < 8; w++) {
        mx12 = fmaxf(mx12, red[0][w]);
        mx21 = fmaxf(mx21, red[1][w]);
    }
    __syncthreads();

    float s12 = 0.0f, s21 = 0.0f;
#pragma unroll
    for (int i = 0; i < PER; i++) {
        v12[i] = __expf(v12[i] - mx12);
        v21[i] = __expf(v21[i] - mx21);
        s12 += v12[i]; s21 += v21[i];
    }
#pragma unroll
    for (int o = 16; o > 0; o >>= 1) {
        s12 += __shfl_xor_sync(0xffffffffu, s12, o);
        s21 += __shfl_xor_sync(0xffffffffu, s21, o);
    }
    if ((t & 31) == 0) { red[0][t >> 5] = s12; red[1][t >> 5] = s21; }
    __syncthreads();
    s12 = red[0][0]; s21 = red[1][0];
#pragma unroll
    for (int w = 1; w < 8; w++) { s12 += red[0][w]; s21 += red[1][w]; }

    const float i12 = 1.0f / s12;
    const float i21 = 1.0f / s21;
#pragma unroll
    for (int i = 0; i < PER; i++) {
        float att = fabsf(v12[i] * i12 - v21[i] * i21);
        oh[t + i * 256] = __float2half_rn(att);
    }
}

// ================= HMMA fp16 multi-term GEMM, 4-stage cp.async =============
// C[m,n] = sum over tiles of A_t[m,k] * B_t[n,k]   (A, B K-major fp16)
// BM=BN=128, BK=32, 8 warps (4M x 2N, 32x64 warp tile), occ 2.
// Tile order TERM-INNER: g -> (k = g/NTERMS, term = g%NTERMS).
// One __syncthreads per K-iter (CUTLASS multistage pattern).
// BIASMODE: 0 none, 1 per-row bias[m]*g_scal[2], 2 per-col bias[n].
// EPI: 0 fp32 C, 1 fp16 hi/lo pair. SWAP: m from blockIdx.x.

#define STAGE_B (2 * 128 * 80)        // A+B bytes per stage = 20480
#define NSTAGE  4
#define SMEM_DYN (NSTAGE * STAGE_B)   // 81920

__device__ __forceinline__ uint32_t smem_u32(const void* p) {
    uint32_t a;
    asm("{ .reg .u64 t; cvta.to.shared.u64 t, %1; cvt.u32.u64 %0, t; }" : "=r"(a) : "l"(p));
    return a;
}
__device__ __forceinline__ void cp16(uint32_t dst, const void* src) {
    asm volatile("cp.async.cg.shared.global [%0], [%1], 16;" :: "r"(dst), "l"(src));
}
__device__ __forceinline__ void ldsm4(uint32_t* r, uint32_t addr) {
    asm volatile("ldmatrix.sync.aligned.m8n8.x4.shared.b16 {%0,%1,%2,%3}, [%4];"
                 : "=r"(r[0]), "=r"(r[1]), "=r"(r[2]), "=r"(r[3]) : "r"(addr));
}
__device__ __forceinline__ void mma16816(float* d, const uint32_t* a, const uint32_t* b) {
    asm volatile(
        "mma.sync.aligned.m16n8k16.row.col.f32.f16.f16.f32 "
        "{%0,%1,%2,%3}, {%4,%5,%6,%7}, {%8,%9}, {%0,%1,%2,%3};"
        : "+f"(d[0]), "+f"(d[1]), "+f"(d[2]), "+f"(d[3])
        : "r"(a[0]), "r"(a[1]), "r"(a[2]), "r"(a[3]), "r"(b[0]), "r"(b[1]));
}

template<int BIASMODE, int EPI, bool SWAP, int NTERMS>
__global__ void __launch_bounds__(256, 2) hgemm_kernel(
    const fp16* __restrict__ a0, const fp16* __restrict__ a1, const fp16* __restrict__ a2,
    const fp16* __restrict__ b0, const fp16* __restrict__ b1, const fp16* __restrict__ b2,
    int nkt, int lda, int ldb, long bsA, long bsB,
    float* __restrict__ C, fp16* __restrict__ Chi, fp16* __restrict__ Clo,
    int ldc, long bsC, const float* __restrict__ bias)
{
    extern __shared__ __align__(16) fp16 dsm[];

    const int tid = threadIdx.x;
    const int wid = tid >> 5;
    const int lane = tid & 31;
    const int wm = wid >> 1;
    const int wn = wid & 1;
    const int m0 = (SWAP ? blockIdx.x : blockIdx.y) * 128;
    const int n0 = (SWAP ? blockIdx.y : blockIdx.x) * 128;
    const int z  = blockIdx.z;

    const uint32_t s0 = smem_u32(dsm);

    float acc[2][8][4];
#pragma unroll
    for (int i = 0; i < 2; i++)
#pragma unroll
        for (int j = 0; j < 8; j++)
#pragma unroll
            for (int q = 0; q < 4; q++) acc[i][j][q] = 0.0f;

    const int lrow0 = tid >> 2;
    const int lch0  = tid & 3;
    auto load_tile = [&](int g, int slot) {
        const int t  = g % NTERMS;
        const int k0 = (g / NTERMS) * 32;
        const fp16* Ap = (t == 0 ? a0 : (t == 1 ? a1 : a2)) + z * bsA + (long)m0 * lda + k0;
        const fp16* Bp = (t == 0 ? b0 : (t == 1 ? b1 : b2)) + z * bsB + (long)n0 * ldb + k0;
        const uint32_t da = s0 + slot * STAGE_B;
        const uint32_t db = da + 128 * 80;
#pragma unroll
        for (int i = 0; i < 2; i++) {
            int row = lrow0 + i * 64;
            cp16(da + row * 80 + lch0 * 16, Ap + (long)row * lda + lch0 * 8);
            cp16(db + row * 80 + lch0 * 16, Bp + (long)row * ldb + lch0 * 8);
        }
        asm volatile("cp.async.commit_group;");
    };

    // preload 3 stages
    load_tile(0, 0);
    if (nkt > 1) load_tile(1, 1);
    if (nkt > 2) load_tile(2, 2);

    for (int g = 0; g < nkt; g++) {
        const int pend = nkt - 1 - g;          // groups issued after g
        if (pend >= 2)      asm volatile("cp.async.wait_group 2;");
        else if (pend == 1) asm volatile("cp.async.wait_group 1;");
        else                asm volatile("cp.async.wait_group 0;");
        __syncthreads();

        if (g + 3 < nkt) load_tile(g + 3, (g + 3) & (NSTAGE - 1));

        const uint32_t da = s0 + (g & (NSTAGE - 1)) * STAGE_B;
        const uint32_t db = da + 128 * 80;
#pragma unroll
        for (int ks = 0; ks < 2; ks++) {
            uint32_t af[2][4];
#pragma unroll
            for (int mt = 0; mt < 2; mt++) {
                int row = wm * 32 + mt * 16 + (lane & 15);
                int kc  = ks * 16 + (lane >> 4) * 8;
                ldsm4(af[mt], da + row * 80 + kc * 2);
            }
            uint32_t bfr[4][4];
#pragma unroll
            for (int p = 0; p < 4; p++) {
                int row = wn * 64 + p * 16 + (lane >> 4) * 8 + (lane & 7);
                int kc  = ks * 16 + ((lane >> 3) & 1) * 8;
                ldsm4(bfr[p], db + row * 80 + kc * 2);
            }
#pragma unroll
            for (int mt = 0; mt < 2; mt++)
#pragma unroll
                for (int p = 0; p < 4; p++) {
                    mma16816(acc[mt][2 * p],     af[mt], &bfr[p][0]);
                    mma16816(acc[mt][2 * p + 1], af[mt], &bfr[p][2]);
                }
        }
        // no trailing barrier: next iter's top barrier orders slot reuse
    }

    // epilogue
#pragma unroll
    for (int mt = 0; mt < 2; mt++) {
        const int mA = m0 + wm * 32 + mt * 16 + (lane >> 2);
        float bvA = 0.0f, bvB = 0.0f;
        if (BIASMODE == 1) { bvA = bias[mA] * g_scal[2]; bvB = bias[mA + 8] * g_scal[2]; }
#pragma unroll
        for (int nt = 0; nt < 8; nt++) {
            const int n = n0 + wn * 64 + nt * 8 + (lane & 3) * 2;
            float c0 = acc[mt][nt][0], c1 = acc[mt][nt][1];
            float c2 = acc[mt][nt][2], c3 = acc[mt][nt][3];
            if (BIASMODE == 1) { c0 += bvA; c1 += bvA; c2 += bvB; c3 += bvB; }
            if (BIASMODE == 2) {
                float b0v = bias[n], b1v = bias[n + 1];
                c0 += b0v; c1 += b1v; c2 += b0v; c3 += b1v;
            }
            if (EPI == 0) {
                float* Cz = C + (long)z * bsC;
                *(float2*)(Cz + (long)mA * ldc + n)       = make_float2(c0, c1);
                *(float2*)(Cz + (long)(mA + 8) * ldc + n) = make_float2(c2, c3);
            } else {
                fp16* Hz = Chi + (long)z * bsC;
                fp16* Lz = Clo + (long)z * bsC;
                fp16 h0, l0, h1, l1, h2, l2, h3, l3;
                split2(c0, h0, l0); split2(c1, h1, l1);
                split2(c2, h2, l2); split2(c3, h3, l3);
                __half2 H0; H0.x = h0; H0.y = h1;
                __half2 H1; H1.x = h2; H1.y = h3;
                __half2 L0; L0.x = l0; L0.y = l1;
                __half2 L1; L1.x = l2; L1.y = l3;
                *(__half2*)(Hz + (long)mA * ldc + n)       = H0;
                *(__half2*)(Hz + (long)(mA + 8) * ldc + n) = H1;
                *(__half2*)(Lz + (long)mA * ldc + n)       = L0;
                *(__half2*)(Lz + (long)(mA + 8) * ldc + n) = L1;
            }
        }
    }
}

// ---------------- launch ----------------
extern "C" void kernel_launch(void* const* d_in, const int* in_sizes, int n_in,
                              void* d_out, int out_size) {
    const float* x1    = (const float*)d_in[0];
    const float* x2    = (const float*)d_in[1];
    const float* Wb    = (const float*)d_in[2];
    const float* bb    = (const float*)d_in[3];
    const float* Wc    = (const float*)d_in[4];
    const float* bc    = (const float*)d_in[5];
    const float* Wdd   = (const float*)d_in[6];
    const float* bd    = (const float*)d_in[7];
    const float* alpha = (const float*)d_in[8];
    const float* beta  = (const float*)d_in[9];
    float* out = (float*)d_out;

    fp16 *xTh, *xTl, *xcTh, *xcTl, *Wbch, *Wbcl, *Wdh, *Wdl, *Ph, *Pl, *Fh, *Fl, *Ah;
    float *S12, *S21, *bias2;
    cudaGetSymbolAddress((void**)&xTh,  g_xTh);
    cudaGetSymbolAddress((void**)&xTl,  g_xTl);
    cudaGetSymbolAddress((void**)&xcTh, g_xcTh);
    cudaGetSymbolAddress((void**)&xcTl, g_xcTl);
    cudaGetSymbolAddress((void**)&Wbch, g_Wbch);
    cudaGetSymbolAddress((void**)&Wbcl, g_Wbcl);
    cudaGetSymbolAddress((void**)&Wdh,  g_Wdh);
    cudaGetSymbolAddress((void**)&Wdl,  g_Wdl);
    cudaGetSymbolAddress((void**)&Ph,   g_Ph);
    cudaGetSymbolAddress((void**)&Pl,   g_Pl);
    cudaGetSymbolAddress((void**)&Fh,   g_Fh);
    cudaGetSymbolAddress((void**)&Fl,   g_Fl);
    cudaGetSymbolAddress((void**)&S12,  g_S12);
    cudaGetSymbolAddress((void**)&S21,  g_S21);
    cudaGetSymbolAddress((void**)&Ah,   g_Ah);
    cudaGetSymbolAddress((void**)&bias2, g_bias2);

    cudaFuncSetAttribute(hgemm_kernel<2, 1, false, 3>,
                         cudaFuncAttributeMaxDynamicSharedMemorySize, SMEM_DYN);
    cudaFuncSetAttribute(hgemm_kernel<1, 1, false, 3>,
                         cudaFuncAttributeMaxDynamicSharedMemorySize, SMEM_DYN);
    cudaFuncSetAttribute(hgemm_kernel<0, 0, false, 3>,
                         cudaFuncAttributeMaxDynamicSharedMemorySize, SMEM_DYN);
    cudaFuncSetAttribute(hgemm_kernel<0, 0, true, 2>,
                         cudaFuncAttributeMaxDynamicSharedMemorySize, SMEM_DYN);

    prep_kernel<<<1, 128>>>(bb, bc, alpha, beta);

    dim3 gT(NPIX / 32, CH / 32, BATCH);
    transcomb_kernel<<<gT, dim3(32, 8)>>>(x1, x2);

    wbc_split_kernel<<<(128 * CH + 255) / 256, 256>>>(Wb, Wc);
    split_kernel<<<(CH * CH + 255) / 256, 256>>>(Wdd, Wdh, Wdl, CH * CH);

    const long bsXT = (long)NPIX * CH;
    const long bsP  = (long)NPIX * 128;
    const long bsF  = (long)CH * NPIX;
    const long bsS  = (long)NPIX * NPIX;

    // P^T = x^T @ Wbc^T (M=4096, N=128, K=512), bias per-col, fp16 epi, 3 terms
    hgemm_kernel<2, 1, false, 3><<<dim3(1, NPIX / 128, 4), 256, SMEM_DYN>>>(
        xTh, xTl, xTh,  Wbch, Wbch, Wbcl,
        3 * CH / 32, CH, CH, bsXT, 0L,
        nullptr, Ph, Pl, 128, bsP, bias2);

    // F = Wdd @ xc + (a+b)*bd (M=512, N=4096, K=512), bias per-row, 3 terms
    hgemm_kernel<1, 1, false, 3><<<dim3(NPIX / 128, CH / 128, BATCH), 256, SMEM_DYN>>>(
        Wdh, Wdl, Wdh,  xcTh, xcTh, xcTl,
        3 * CH / 32, CH, CH, 0L, bsXT,
        nullptr, Fh, Fl, NPIX, bsF, bd);

    // logits S12[n,m] = A1[n,:]·B2[m,:]  (M=N=4096, K=64), 3 terms
    dim3 gS(NPIX / 128, NPIX / 128, BATCH);
    hgemm_kernel<0, 0, false, 3><<<gS, 256, SMEM_DYN>>>(
        Ph, Pl, Ph,  Ph + 2 * bsP + 64, Ph + 2 * bsP + 64, Pl + 2 * bsP + 64,
        6, 128, 128, bsP, bsP,
        S12, nullptr, nullptr, NPIX, bsS, nullptr);
    hgemm_kernel<0, 0, false, 3><<<gS, 256, SMEM_DYN>>>(
        Ph + 2 * bsP, Pl + 2 * bsP, Ph + 2 * bsP,  Ph + 64, Ph + 64, Pl + 64,
        6, 128, 128, bsP, bsP,
        S21, nullptr, nullptr, NPIX, bsS, nullptr);

    // att = |softmax(S12)-softmax(S21)| -> fp16 (hi only)
    softdiff_kernel<<<BATCH * NPIX, 256>>>();

    // out[c,n] = sum_m F[c,m]*att[n,m]  (M=512, N=4096), 2 TERMS:
    // (Fh,Ah) + (Fl,Ah); dropped (Fh,Al) term is ~2^-12 of result.
    // SWAP: x walks c-blocks so att tiles are L2-shared; term-inner makes the
    // same Ah(k) tile reused on consecutive iterations.
    hgemm_kernel<0, 0, true, 2><<<dim3(CH / 128, NPIX / 128, BATCH), 256, SMEM_DYN>>>(
        Fh, Fl, Fh,  Ah, Ah, Ah,
        2 * NPIX / 32, NPIX, NPIX, bsF, bsS,
        out, nullptr, nullptr, NPIX, bsF, nullptr);
}

// round 9
// speedup vs baseline: 1.9414x; 1.2714x over previous
#include <cuda_runtime.h>
#include <cuda_fp16.h>
#include <math.h>
#include <stdint.h>

#define BATCH 2
#define CH    512
#define CQ    64
#define NPIX  4096

typedef __half fp16;

// ---------------- static scratch ----------------
__device__ __align__(128) fp16  g_xTh[4L * NPIX * CH];   // [which*2+b][n][c] hi
__device__ __align__(128) fp16  g_xTl[4L * NPIX * CH];
__device__ __align__(128) fp16  g_xcTh[2L * NPIX * CH];  // [b][n][c]
__device__ __align__(128) fp16  g_xcTl[2L * NPIX * CH];
__device__ __align__(128) fp16  g_Wbch[128 * CH];        // [o(128)][c] (Wb;Wc)
__device__ __align__(128) fp16  g_Wbcl[128 * CH];
__device__ __align__(128) fp16  g_Wdh[CH * CH];
__device__ __align__(128) fp16  g_Wdl[CH * CH];
__device__ __align__(128) fp16  g_Ph[4L * NPIX * 128];   // [which*2+b][n][o]
__device__ __align__(128) fp16  g_Pl[4L * NPIX * 128];
__device__ __align__(128) fp16  g_Fh[(long)BATCH * CH * NPIX];  // [b][c][n]
__device__ __align__(128) float g_S12[(size_t)BATCH * NPIX * NPIX];
__device__ __align__(128) float g_S21[(size_t)BATCH * NPIX * NPIX];
__device__ __align__(128) fp16  g_Ah[(size_t)BATCH * NPIX * NPIX];
__device__ float g_scal[4];
__device__ float g_bias2[128];

__device__ __forceinline__ void split2(float v, fp16& h, fp16& l) {
    h = __float2half_rn(v);
    l = __float2half_rn(v - __half2float(h));
}

// ---------------- prep ----------------
__global__ void prep_kernel(const float* bb, const float* bc,
                            const float* a, const float* b) {
    int t = threadIdx.x;
    if (t < 64)       g_bias2[t] = bb[t];
    else if (t < 128) g_bias2[t] = bc[t - 64];
    if (t == 0) { g_scal[0] = a[0]; g_scal[1] = b[0]; g_scal[2] = a[0] + b[0]; }
}

__global__ void split_kernel(const float* __restrict__ src,
                             fp16* __restrict__ hi, fp16* __restrict__ lo, int n) {
    int i = blockIdx.x * blockDim.x + threadIdx.x;
    if (i < n) { fp16 h, l; split2(src[i], h, l); hi[i] = h; lo[i] = l; }
}

__global__ void wbc_split_kernel(const float* __restrict__ Wb,
                                 const float* __restrict__ Wc) {
    int i = blockIdx.x * blockDim.x + threadIdx.x;
    if (i < 128 * CH) {
        float v = (i < 64 * CH) ? Wb[i] : Wc[i - 64 * CH];
        fp16 h, l; split2(v, h, l);
        g_Wbch[i] = h; g_Wbcl[i] = l;
    }
}

// ---------------- combine + transpose + split ----------------
__global__ void __launch_bounds__(256) transcomb_kernel(
    const float* __restrict__ x1, const float* __restrict__ x2) {
    __shared__ float t1[32][33], t2[32][33];
    const int b  = blockIdx.z;
    const int n0 = blockIdx.x * 32;
    const int k0 = blockIdx.y * 32;
    const int tx = threadIdx.x, ty = threadIdx.y;
    const float al = g_scal[0], be = g_scal[1];

    const long inb = (long)b * CH * NPIX;
#pragma unroll
    for (int it = 0; it < 4; it++) {
        int ki = ty + it * 8;
        t1[ki][tx] = x1[inb + (long)(k0 + ki) * NPIX + n0 + tx];
        t2[ki][tx] = x2[inb + (long)(k0 + ki) * NPIX + n0 + tx];
    }
    __syncthreads();

#pragma unroll
    for (int it = 0; it < 4; it++) {
        int ni = ty + it * 8;
        float v1 = t1[tx][ni];
        float v2 = t2[tx][ni];
        float vc = al * v1 + be * v2;
        long o1 = ((long)b * NPIX + n0 + ni) * CH + k0 + tx;
        long o2 = ((long)(2 + b) * NPIX + n0 + ni) * CH + k0 + tx;
        long oc = ((long)b * NPIX + n0 + ni) * CH + k0 + tx;
        fp16 h, l;
        split2(v1, h, l); g_xTh[o1] = h; g_xTl[o1] = l;
        split2(v2, h, l); g_xTh[o2] = h; g_xTl[o2] = l;
        split2(vc, h, l); g_xcTh[oc] = h; g_xcTl[oc] = l;
    }
}

// ---------------- fused double-softmax abs-diff -> fp16 (vectorized) -------
__global__ void __launch_bounds__(256) softdiff_kernel() {
    const long row = blockIdx.x;
    const float4* p12 = (const float4*)(g_S12 + row * (long)NPIX);
    const float4* p21 = (const float4*)(g_S21 + row * (long)NPIX);
    __half2* oh = (__half2*)(g_Ah + row * (long)NPIX);
    const int t = threadIdx.x;
    constexpr int PER = NPIX / (256 * 4);   // 4 float4s per thread per array

    float4 v12[PER], v21[PER];
    float mx12 = -1e30f, mx21 = -1e30f;
#pragma unroll
    for (int i = 0; i < PER; i++) {
        v12[i] = p12[t + i * 256];
        v21[i] = p21[t + i * 256];
        mx12 = fmaxf(mx12, fmaxf(fmaxf(v12[i].x, v12[i].y), fmaxf(v12[i].z, v12[i].w)));
        mx21 = fmaxf(mx21, fmaxf(fmaxf(v21[i].x, v21[i].y), fmaxf(v21[i].z, v21[i].w)));
    }
    __shared__ float red[2][8];
#pragma unroll
    for (int o = 16; o > 0; o >>= 1) {
        mx12 = fmaxf(mx12, __shfl_xor_sync(0xffffffffu, mx12, o));
        mx21 = fmaxf(mx21, __shfl_xor_sync(0xffffffffu, mx21, o));
    }
    if ((t & 31) == 0) { red[0][t >> 5] = mx12; red[1][t >> 5] = mx21; }
    __syncthreads();
    mx12 = red[0][0]; mx21 = red[1][0];
#pragma unroll
    for (int w = 1; w < 8; w++) {
        mx12 = fmaxf(mx12, red[0][w]);
        mx21 = fmaxf(mx21, red[1][w]);
    }
    __syncthreads();

    float s12 = 0.0f, s21 = 0.0f;
#pragma unroll
    for (int i = 0; i < PER; i++) {
        v12[i].x = __expf(v12[i].x - mx12); v12[i].y = __expf(v12[i].y - mx12);
        v12[i].z = __expf(v12[i].z - mx12); v12[i].w = __expf(v12[i].w - mx12);
        v21[i].x = __expf(v21[i].x - mx21); v21[i].y = __expf(v21[i].y - mx21);
        v21[i].z = __expf(v21[i].z - mx21); v21[i].w = __expf(v21[i].w - mx21);
        s12 += (v12[i].x + v12[i].y) + (v12[i].z + v12[i].w);
        s21 += (v21[i].x + v21[i].y) + (v21[i].z + v21[i].w);
    }
#pragma unroll
    for (int o = 16; o > 0; o >>= 1) {
        s12 += __shfl_xor_sync(0xffffffffu, s12, o);
        s21 += __shfl_xor_sync(0xffffffffu, s21, o);
    }
    if ((t & 31) == 0) { red[0][t >> 5] = s12; red[1][t >> 5] = s21; }
    __syncthreads();
    s12 = red[0][0]; s21 = red[1][0];
#pragma unroll
    for (int w = 1; w < 8; w++) { s12 += red[0][w]; s21 += red[1][w]; }

    const float i12 = 1.0f / s12;
    const float i21 = 1.0f / s21;
#pragma unroll
    for (int i = 0; i < PER; i++) {
        float a0 = fabsf(v12[i].x * i12 - v21[i].x * i21);
        float a1 = fabsf(v12[i].y * i12 - v21[i].y * i21);
        float a2 = fabsf(v12[i].z * i12 - v21[i].z * i21);
        float a3 = fabsf(v12[i].w * i12 - v21[i].w * i21);
        __half2 h0; h0.x = __float2half_rn(a0); h0.y = __float2half_rn(a1);
        __half2 h1; h1.x = __float2half_rn(a2); h1.y = __float2half_rn(a3);
        oh[(t + i * 256) * 2]     = h0;
        oh[(t + i * 256) * 2 + 1] = h1;
    }
}

// ================= HMMA fp16 multi-term GEMM, 4-stage cp.async =============
// C[m,n] = sum over tiles of A_t[m,k] * B_t[n,k]   (A, B K-major fp16)
// BM=BN=128, BK=32, 8 warps (4M x 2N, 32x64 warp tile), occ 2.
// Tile order TERM-INNER: g -> (k = g/NTERMS, term = g%NTERMS).
// BIASMODE: 0 none, 1 per-row bias[m]*g_scal[2], 2 per-col bias[n].
// EPI: 0 fp32 C, 1 fp16 hi/lo pair, 2 fp16 hi only. SWAP: m from blockIdx.x.

#define STAGE_B (2 * 128 * 80)        // A+B bytes per stage = 20480
#define NSTAGE  4
#define SMEM_DYN (NSTAGE * STAGE_B)   // 81920

__device__ __forceinline__ uint32_t smem_u32(const void* p) {
    uint32_t a;
    asm("{ .reg .u64 t; cvta.to.shared.u64 t, %1; cvt.u32.u64 %0, t; }" : "=r"(a) : "l"(p));
    return a;
}
__device__ __forceinline__ void cp16(uint32_t dst, const void* src) {
    asm volatile("cp.async.cg.shared.global [%0], [%1], 16;" :: "r"(dst), "l"(src));
}
__device__ __forceinline__ void ldsm4(uint32_t* r, uint32_t addr) {
    asm volatile("ldmatrix.sync.aligned.m8n8.x4.shared.b16 {%0,%1,%2,%3}, [%4];"
                 : "=r"(r[0]), "=r"(r[1]), "=r"(r[2]), "=r"(r[3]) : "r"(addr));
}
__device__ __forceinline__ void mma16816(float* d, const uint32_t* a, const uint32_t* b) {
    asm volatile(
        "mma.sync.aligned.m16n8k16.row.col.f32.f16.f16.f32 "
        "{%0,%1,%2,%3}, {%4,%5,%6,%7}, {%8,%9}, {%0,%1,%2,%3};"
        : "+f"(d[0]), "+f"(d[1]), "+f"(d[2]), "+f"(d[3])
        : "r"(a[0]), "r"(a[1]), "r"(a[2]), "r"(a[3]), "r"(b[0]), "r"(b[1]));
}

template<int BIASMODE, int EPI, bool SWAP, int NTERMS>
__global__ void __launch_bounds__(256, 2) hgemm_kernel(
    const fp16* __restrict__ a0, const fp16* __restrict__ a1, const fp16* __restrict__ a2,
    const fp16* __restrict__ b0, const fp16* __restrict__ b1, const fp16* __restrict__ b2,
    int nkt, int lda, int ldb, long bsA, long bsB,
    float* __restrict__ C, fp16* __restrict__ Chi, fp16* __restrict__ Clo,
    int ldc, long bsC, const float* __restrict__ bias)
{
    extern __shared__ __align__(16) fp16 dsm[];

    const int tid = threadIdx.x;
    const int wid = tid >> 5;
    const int lane = tid & 31;
    const int wm = wid >> 1;
    const int wn = wid & 1;
    const int m0 = (SWAP ? blockIdx.x : blockIdx.y) * 128;
    const int n0 = (SWAP ? blockIdx.y : blockIdx.x) * 128;
    const int z  = blockIdx.z;

    const uint32_t s0 = smem_u32(dsm);

    float acc[2][8][4];
#pragma unroll
    for (int i = 0; i < 2; i++)
#pragma unroll
        for (int j = 0; j < 8; j++)
#pragma unroll
            for (int q = 0; q < 4; q++) acc[i][j][q] = 0.0f;

    const int lrow0 = tid >> 2;
    const int lch0  = tid & 3;
    auto load_tile = [&](int g, int slot) {
        const int t  = g % NTERMS;
        const int k0 = (g / NTERMS) * 32;
        const fp16* Ap = (t == 0 ? a0 : (t == 1 ? a1 : a2)) + z * bsA + (long)m0 * lda + k0;
        const fp16* Bp = (t == 0 ? b0 : (t == 1 ? b1 : b2)) + z * bsB + (long)n0 * ldb + k0;
        const uint32_t da = s0 + slot * STAGE_B;
        const uint32_t db = da + 128 * 80;
#pragma unroll
        for (int i = 0; i < 2; i++) {
            int row = lrow0 + i * 64;
            cp16(da + row * 80 + lch0 * 16, Ap + (long)row * lda + lch0 * 8);
            cp16(db + row * 80 + lch0 * 16, Bp + (long)row * ldb + lch0 * 8);
        }
        asm volatile("cp.async.commit_group;");
    };

    load_tile(0, 0);
    if (nkt > 1) load_tile(1, 1);
    if (nkt > 2) load_tile(2, 2);

    for (int g = 0; g < nkt; g++) {
        const int pend = nkt - 1 - g;
        if (pend >= 2)      asm volatile("cp.async.wait_group 2;");
        else if (pend == 1) asm volatile("cp.async.wait_group 1;");
        else                asm volatile("cp.async.wait_group 0;");
        __syncthreads();

        if (g + 3 < nkt) load_tile(g + 3, (g + 3) & (NSTAGE - 1));

        const uint32_t da = s0 + (g & (NSTAGE - 1)) * STAGE_B;
        const uint32_t db = da + 128 * 80;
#pragma unroll
        for (int ks = 0; ks < 2; ks++) {
            uint32_t af[2][4];
#pragma unroll
            for (int mt = 0; mt < 2; mt++) {
                int row = wm * 32 + mt * 16 + (lane & 15);
                int kc  = ks * 16 + (lane >> 4) * 8;
                ldsm4(af[mt], da + row * 80 + kc * 2);
            }
            uint32_t bfr[4][4];
#pragma unroll
            for (int p = 0; p < 4; p++) {
                int row = wn * 64 + p * 16 + (lane >> 4) * 8 + (lane & 7);
                int kc  = ks * 16 + ((lane >> 3) & 1) * 8;
                ldsm4(bfr[p], db + row * 80 + kc * 2);
            }
#pragma unroll
            for (int mt = 0; mt < 2; mt++)
#pragma unroll
                for (int p = 0; p < 4; p++) {
                    mma16816(acc[mt][2 * p],     af[mt], &bfr[p][0]);
                    mma16816(acc[mt][2 * p + 1], af[mt], &bfr[p][2]);
                }
        }
    }

    // epilogue
#pragma unroll
    for (int mt = 0; mt < 2; mt++) {
        const int mA = m0 + wm * 32 + mt * 16 + (lane >> 2);
        float bvA = 0.0f, bvB = 0.0f;
        if (BIASMODE == 1) { bvA = bias[mA] * g_scal[2]; bvB = bias[mA + 8] * g_scal[2]; }
#pragma unroll
        for (int nt = 0; nt < 8; nt++) {
            const int n = n0 + wn * 64 + nt * 8 + (lane & 3) * 2;
            float c0 = acc[mt][nt][0], c1 = acc[mt][nt][1];
            float c2 = acc[mt][nt][2], c3 = acc[mt][nt][3];
            if (BIASMODE == 1) { c0 += bvA; c1 += bvA; c2 += bvB; c3 += bvB; }
            if (BIASMODE == 2) {
                float b0v = bias[n], b1v = bias[n + 1];
                c0 += b0v; c1 += b1v; c2 += b0v; c3 += b1v;
            }
            if (EPI == 0) {
                float* Cz = C + (long)z * bsC;
                *(float2*)(Cz + (long)mA * ldc + n)       = make_float2(c0, c1);
                *(float2*)(Cz + (long)(mA + 8) * ldc + n) = make_float2(c2, c3);
            } else if (EPI == 2) {
                fp16* Hz = Chi + (long)z * bsC;
                __half2 H0; H0.x = __float2half_rn(c0); H0.y = __float2half_rn(c1);
                __half2 H1; H1.x = __float2half_rn(c2); H1.y = __float2half_rn(c3);
                *(__half2*)(Hz + (long)mA * ldc + n)       = H0;
                *(__half2*)(Hz + (long)(mA + 8) * ldc + n) = H1;
            } else {
                fp16* Hz = Chi + (long)z * bsC;
                fp16* Lz = Clo + (long)z * bsC;
                fp16 h0, l0, h1, l1, h2, l2, h3, l3;
                split2(c0, h0, l0); split2(c1, h1, l1);
                split2(c2, h2, l2); split2(c3, h3, l3);
                __half2 H0; H0.x = h0; H0.y = h1;
                __half2 H1; H1.x = h2; H1.y = h3;
                __half2 L0; L0.x = l0; L0.y = l1;
                __half2 L1; L1.x = l2; L1.y = l3;
                *(__half2*)(Hz + (long)mA * ldc + n)       = H0;
                *(__half2*)(Hz + (long)(mA + 8) * ldc + n) = H1;
                *(__half2*)(Lz + (long)mA * ldc + n)       = L0;
                *(__half2*)(Lz + (long)(mA + 8) * ldc + n) = L1;
            }
        }
    }
}

// ---------------- launch ----------------
extern "C" void kernel_launch(void* const* d_in, const int* in_sizes, int n_in,
                              void* d_out, int out_size) {
    const float* x1    = (const float*)d_in[0];
    const float* x2    = (const float*)d_in[1];
    const float* Wb    = (const float*)d_in[2];
    const float* bb    = (const float*)d_in[3];
    const float* Wc    = (const float*)d_in[4];
    const float* bc    = (const float*)d_in[5];
    const float* Wdd   = (const float*)d_in[6];
    const float* bd    = (const float*)d_in[7];
    const float* alpha = (const float*)d_in[8];
    const float* beta  = (const float*)d_in[9];
    float* out = (float*)d_out;

    fp16 *xTh, *xTl, *xcTh, *xcTl, *Wbch, *Wbcl, *Wdh, *Wdl, *Ph, *Pl, *Fh, *Ah;
    float *S12, *S21, *bias2;
    cudaGetSymbolAddress((void**)&xTh,  g_xTh);
    cudaGetSymbolAddress((void**)&xTl,  g_xTl);
    cudaGetSymbolAddress((void**)&xcTh, g_xcTh);
    cudaGetSymbolAddress((void**)&xcTl, g_xcTl);
    cudaGetSymbolAddress((void**)&Wbch, g_Wbch);
    cudaGetSymbolAddress((void**)&Wbcl, g_Wbcl);
    cudaGetSymbolAddress((void**)&Wdh,  g_Wdh);
    cudaGetSymbolAddress((void**)&Wdl,  g_Wdl);
    cudaGetSymbolAddress((void**)&Ph,   g_Ph);
    cudaGetSymbolAddress((void**)&Pl,   g_Pl);
    cudaGetSymbolAddress((void**)&Fh,   g_Fh);
    cudaGetSymbolAddress((void**)&S12,  g_S12);
    cudaGetSymbolAddress((void**)&S21,  g_S21);
    cudaGetSymbolAddress((void**)&Ah,   g_Ah);
    cudaGetSymbolAddress((void**)&bias2, g_bias2);

    cudaFuncSetAttribute(hgemm_kernel<2, 1, false, 3>,
                         cudaFuncAttributeMaxDynamicSharedMemorySize, SMEM_DYN);
    cudaFuncSetAttribute(hgemm_kernel<1, 2, false, 3>,
                         cudaFuncAttributeMaxDynamicSharedMemorySize, SMEM_DYN);
    cudaFuncSetAttribute(hgemm_kernel<0, 0, false, 3>,
                         cudaFuncAttributeMaxDynamicSharedMemorySize, SMEM_DYN);
    cudaFuncSetAttribute(hgemm_kernel<0, 0, true, 1>,
                         cudaFuncAttributeMaxDynamicSharedMemorySize, SMEM_DYN);

    prep_kernel<<<1, 128>>>(bb, bc, alpha, beta);

    dim3 gT(NPIX / 32, CH / 32, BATCH);
    transcomb_kernel<<<gT, dim3(32, 8)>>>(x1, x2);

    wbc_split_kernel<<<(128 * CH + 255) / 256, 256>>>(Wb, Wc);
    split_kernel<<<(CH * CH + 255) / 256, 256>>>(Wdd, Wdh, Wdl, CH * CH);

    const long bsXT = (long)NPIX * CH;
    const long bsP  = (long)NPIX * 128;
    const long bsF  = (long)CH * NPIX;
    const long bsS  = (long)NPIX * NPIX;

    // P^T = x^T @ Wbc^T (M=4096, N=128, K=512), bias per-col, hi/lo epi, 3 terms
    hgemm_kernel<2, 1, false, 3><<<dim3(1, NPIX / 128, 4), 256, SMEM_DYN>>>(
        xTh, xTl, xTh,  Wbch, Wbch, Wbcl,
        3 * CH / 32, CH, CH, bsXT, 0L,
        nullptr, Ph, Pl, 128, bsP, bias2);

    // F = Wdd @ xc + (a+b)*bd (M=512, N=4096, K=512), hi-only epi, 3 terms
    hgemm_kernel<1, 2, false, 3><<<dim3(NPIX / 128, CH / 128, BATCH), 256, SMEM_DYN>>>(
        Wdh, Wdl, Wdh,  xcTh, xcTh, xcTl,
        3 * CH / 32, CH, CH, 0L, bsXT,
        nullptr, Fh, nullptr, NPIX, bsF, bd);

    // logits S12[n,m] = A1[n,:]·B2[m,:]  (M=N=4096, K=64), 3 terms (full acc)
    dim3 gS(NPIX / 128, NPIX / 128, BATCH);
    hgemm_kernel<0, 0, false, 3><<<gS, 256, SMEM_DYN>>>(
        Ph, Pl, Ph,  Ph + 2 * bsP + 64, Ph + 2 * bsP + 64, Pl + 2 * bsP + 64,
        6, 128, 128, bsP, bsP,
        S12, nullptr, nullptr, NPIX, bsS, nullptr);
    hgemm_kernel<0, 0, false, 3><<<gS, 256, SMEM_DYN>>>(
        Ph + 2 * bsP, Pl + 2 * bsP, Ph + 2 * bsP,  Ph + 64, Ph + 64, Pl + 64,
        6, 128, 128, bsP, bsP,
        S21, nullptr, nullptr, NPIX, bsS, nullptr);

    // att = |softmax(S12)-softmax(S21)| -> fp16 (hi only, vectorized)
    softdiff_kernel<<<BATCH * NPIX, 256>>>();

    // out[c,n] = sum_m Fh[c,m]*Ah[n,m]  (M=512, N=4096, K=4096), 1 TERM
    // SWAP: x walks c-blocks so att tiles are L2-shared by the 4 consumers.
    hgemm_kernel<0, 0, true, 1><<<dim3(CH / 128, NPIX / 128, BATCH), 256, SMEM_DYN>>>(
        Fh, Fh, Fh,  Ah, Ah, Ah,
        NPIX / 32, NPIX, NPIX, bsF, bsS,
        out, nullptr, nullptr, NPIX, bsF, nullptr);
}